// round 5
// baseline (speedup 1.0000x reference)
#include <cuda_runtime.h>
#include <math.h>

#define BN 2
#define KC 12
#define HH 120
#define WW 160
#define HW (HH*WW)          // 19200
#define NB 100
#define DD 128
#define NVOX (DD*DD*DD)
#define NVOXB (BN*NVOX)     // 4194304
#define NW 4                // 32-bit words per x-row
#define ROWW (NW*DD)        // word stride per z-slice = 512
#define NWORDS (NVOXB/32)   // 131072
#define WPB 65536           // words per batch
#define FEAT_ELEMS (BN*15*NB*HW)
#define FK_OFF FEAT_ELEMS
#define MASK_OFF (FEAT_ELEMS + NVOXB)

// ---------------- scratch (device globals; no allocations) ----------------
__device__ float          g_sm[BN*KC*HW];   // softmax features
__device__ int            g_di[BN*HW];      // depth_index
__device__ float          g_sd[BN*HW];      // clamped depth -> stuff_depth
__device__ float          g_sx[BN*WW];
__device__ float          g_sy[BN*HH];
__device__ unsigned int   g_pf[NWORDS];     // packed feat_kept
__device__ unsigned int   g_pk[NWORDS];     // packed kept
__device__ unsigned int   g_pa[NWORDS];     // packed padding_kept
__device__ unsigned int   g_pb[NWORDS];     // packed union
__device__ int            g_bp[BN];

// ---------------- stage A: fused 2D front-end (one block per batch) ----------------
__device__ void find_none_dev(const float* a, int n, float* out){
    float suf[WW];
    float run = INFINITY;
    for (int ii = n-1; ii >= 0; ii--){
        suf[ii] = run;
        float av = (a[ii] != 0.f) ? a[ii] : INFINITY;
        run = fminf(run, av);
    }
    float m = INFINITY;
    for (int ii = 0; ii < n; ii++){
        float l = isinf(m)      ? 0.f : m;
        float r = isinf(suf[ii])? 0.f : suf[ii];
        float val = (a[ii] == 0.f) ? fmaxf(l, r) : a[ii];
        if (val != 0.f) m = fminf(m, val);
        out[ii] = val;
    }
}

__global__ void k_front(const float* __restrict__ sem, const float* __restrict__ depth){
    __shared__ unsigned char s_sind[HW];
    __shared__ float ymax[HH], xmax[WW], colm[WW], rowm[HH];
    __shared__ float vy, vyr, vx, vxr;
    int b = blockIdx.x, tid = threadIdx.x, nt = blockDim.x;
    if (tid == 0) g_bp[b] = 0;

    // phase 1: softmax/argmax/depth-index
    for (int p = tid; p < HW; p += nt){
        const float* s = sem + (size_t)b*KC*HW + p;
        float v[KC]; float mx = -1e30f; int am = 0;
        #pragma unroll
        for (int k = 0; k < KC; k++){ v[k] = s[(size_t)k*HW]; if (v[k] > mx){ mx = v[k]; am = k; } }
        float sum = 0.f;
        #pragma unroll
        for (int k = 0; k < KC; k++){ v[k] = expf(v[k]-mx); sum += v[k]; }
        float inv = 1.f/sum;
        float* o = g_sm + (size_t)b*KC*HW + p;
        #pragma unroll
        for (int k = 0; k < KC; k++) o[(size_t)k*HW] = v[k]*inv;
        s_sind[p] = (unsigned char)(am >= 10);
        float dc = fminf(depth[b*HW + p], 6.f);
        g_di[b*HW + p] = (int)(dc/6.f*100.f);
        g_sd[b*HW + p] = dc;
    }
    __syncthreads();

    // phase 2: 5x5 erosion -> stuff_depth (zero non-stuff pixels)
    for (int p = tid; p < HW; p += nt){
        int h = p / WW, w = p - h*WW;
        bool all1 = true;
        #pragma unroll
        for (int dh = -2; dh <= 2; dh++){
            int h2 = h + dh; if (h2 < 0 || h2 >= HH) continue;
            #pragma unroll
            for (int dw = -2; dw <= 2; dw++){
                int w2 = w + dw; if (w2 < 0 || w2 >= WW) continue;
                if (!s_sind[h2*WW + w2]) all1 = false;
            }
        }
        if (!all1) g_sd[b*HW + p] = 0.f;
    }
    __syncthreads();

    // phase 3: axis maxes
    const float* sd = g_sd + b*HW;
    for (int h = tid; h < HH; h += nt){
        float m = 0.f; for (int w = 0; w < WW; w++) m = fmaxf(m, sd[h*WW+w]); ymax[h] = m;
    }
    for (int w = tid; w < WW; w += nt){
        float m = 0.f; for (int h = 0; h < HH; h++) m = fmaxf(m, sd[h*WW+w]); xmax[w] = m;
    }
    __syncthreads();
    if (tid == 0){
        float a = 0.f; for (int h = 0; h < HH; h++)      if (ymax[h] != 0.f){ a = ymax[h]; break; } vy  = a;
        a = 0.f;       for (int h = HH-1; h >= 0; h--)   if (ymax[h] != 0.f){ a = ymax[h]; break; } vyr = a;
        a = 0.f;       for (int w = 0; w < WW; w++)      if (xmax[w] != 0.f){ a = xmax[w]; break; } vx  = a;
        a = 0.f;       for (int w = WW-1; w >= 0; w--)   if (xmax[w] != 0.f){ a = xmax[w]; break; } vxr = a;
    }
    __syncthreads();
    // border-padded value; column fills override row fills at corners
    auto sdval = [&](int h, int w) -> float {
        float v = sd[h*WW + w];
        if (w == 0)      return (v != 0.f) ? v : vx;
        if (w == WW-1)   return (v != 0.f) ? v : vxr;
        if (h == 0)      return (v != 0.f) ? v : vy;
        if (h == HH-1)   return (v != 0.f) ? v : vyr;
        return v;
    };
    for (int w = tid; w < WW; w += nt){
        float m = 0.f; for (int h = 0; h < HH; h++) m = fmaxf(m, sdval(h, w)); colm[w] = m;
    }
    for (int h = tid; h < HH; h += nt){
        float m = 0.f; for (int w = 0; w < WW; w++) m = fmaxf(m, sdval(h, w)); rowm[h] = m;
    }
    __syncthreads();
    if (tid == 0)  find_none_dev(colm, WW, g_sx + b*WW);
    if (tid == 32) find_none_dev(rowm, HH, g_sy + b*HH);
}

// ---------------- stage B: features (block (160,2), 10 d-bins per thread) ----------------
__global__ void k_feat(const float* __restrict__ occ, float* __restrict__ out){
    int p4 = blockIdx.x*160 + threadIdx.x;           // 0..4799
    int d0 = blockIdx.y*20 + threadIdx.y*10;         // 0..90 step 10
    int cz = blockIdx.z; int b = cz/15, c = cz - b*15;
    float4* ob = (float4*)out + (size_t)cz*NB*(HW/4) + p4;
    if (c < KC){
        float4 o = ((const float4*)g_sm)[(size_t)(b*KC + c)*(HW/4) + p4];
        #pragma unroll
        for (int q = 0; q < 10; q++)
            ob[(size_t)(d0+q)*(HW/4)] = o;
    } else if (c == 13){
        const int4 di4 = ((const int4*)g_di)[b*(HW/4) + p4];
        #pragma unroll
        for (int q = 0; q < 10; q++){
            int d = d0 + q;
            float4 o;
            o.x = (d > di4.x) ? 1.f : ((d < di4.x) ? -1.f : 0.f);
            o.y = (d > di4.y) ? 1.f : ((d < di4.y) ? -1.f : 0.f);
            o.z = (d > di4.z) ? 1.f : ((d < di4.z) ? -1.f : 0.f);
            o.w = (d > di4.w) ? 1.f : ((d < di4.w) ? -1.f : 0.f);
            ob[(size_t)d*(HW/4)] = o;
        }
    } else if (c == 14){
        const int4 di4 = ((const int4*)g_di)[b*(HW/4) + p4];
        #pragma unroll
        for (int q = 0; q < 10; q++){
            int d = d0 + q;
            float4 o;
            o.x = fabsf((float)(d - di4.x)*0.06f);
            o.y = fabsf((float)(d - di4.y)*0.06f);
            o.z = fabsf((float)(d - di4.z)*0.06f);
            o.w = fabsf((float)(d - di4.w)*0.06f);
            ob[(size_t)d*(HW/4)] = o;
        }
    } else { // c == 12 : depth_weight
        int h = p4/40, w0 = (p4 - h*40)*4;
        float sy = g_sy[b*HH + h];
        const int4 di4 = ((const int4*)g_di)[b*(HW/4) + p4];
        int di[4] = {di4.x, di4.y, di4.z, di4.w};
        int dmb[4];
        #pragma unroll
        for (int l = 0; l < 4; l++)
            dmb[l] = (int)(fminf(g_sx[b*WW + w0 + l], sy)/6.f*100.f);
        const float4* occ4 = (const float4*)occ + (size_t)b*NB*(HW/4) + p4;
        #pragma unroll
        for (int q = 0; q < 10; q++){
            int d = d0 + q;
            float4 ov = occ4[(size_t)d*(HW/4)];
            float ovv[4] = {ov.x, ov.y, ov.z, ov.w};
            float res[4];
            #pragma unroll
            for (int l = 0; l < 4; l++){
                bool kp = (d > di[l] - 3) && (d < dmb[l] + 5);
                res[l] = kp ? (1.f/(1.f + expf(-ovv[l]))) : 0.f;
            }
            ob[(size_t)d*(HW/4)] = make_float4(res[0], res[1], res[2], res[3]);
        }
    }
}

// ---------------- stage C: voxel gather -> feat_kept (predicated + ballot pack) ----------------
__global__ void k_voxel(const float4* __restrict__ mapping,
                        const unsigned int* __restrict__ kept,
                        float* __restrict__ out){
    int v = blockIdx.x*blockDim.x + threadIdx.x;
    bool kp = (kept[v] != 0u);
    bool fk = false;
    if (kp){
        float4 m = mapping[v];
        int b = (int)m.x, x = (int)m.y, y = (int)m.z;
        int didx = (int)(m.w*100.f/6.f);
        int di  = g_di[b*HW + y*WW + x];
        int dmb = (int)(fminf(g_sx[b*WW + x], g_sy[b*HH + y])/6.f*100.f);
        fk = (didx > di - 3) && (didx < dmb + 5);
    }
    unsigned bf = __ballot_sync(0xffffffffu, fk);
    unsigned bk = __ballot_sync(0xffffffffu, kp);
    if ((threadIdx.x & 31) == 0){
        g_pf[v >> 5] = bf;
        g_pk[v >> 5] = bk;
    }
    out[FK_OFF + v] = fk ? 1.f : 0.f;
}

// ---------------- fused packed 5^3 dilation: (z,y) word ORs + x via shuffles ----------------
__device__ __forceinline__ unsigned dil3d(const unsigned int* in, int i){
    int t = i >> 2;
    int y = t & (DD-1);
    int z = (t >> 7) & (DD-1);
    unsigned zy = 0;
    #pragma unroll
    for (int dz = -2; dz <= 2; dz++){
        int zz = z + dz; if (zz < 0 || zz >= DD) continue;
        #pragma unroll
        for (int dy = -2; dy <= 2; dy++){
            int yy = y + dy; if (yy < 0 || yy >= DD) continue;
            zy |= in[i + (dz*DD + dy)*NW];
        }
    }
    // x-dilation: an x-row is NW=4 consecutive words, aligned to 4-lane groups
    int wx = i & (NW-1);
    unsigned p = __shfl_up_sync(0xffffffffu, zy, 1);
    unsigned n = __shfl_down_sync(0xffffffffu, zy, 1);
    if (wx == 0)    p = 0u;
    if (wx == NW-1) n = 0u;
    return zy | (zy<<1) | (zy<<2) | (zy>>1) | (zy>>2)
              | (p>>31) | (p>>30) | (n<<31) | (n<<30);
}

// padding_kept = dil3d(feat_kept) & kept; popcount -> g_bp; &= ~feat_kept
__global__ void k_dpk(){
    __shared__ int sc;
    int i = blockIdx.x*256 + threadIdx.x;
    if (threadIdx.x == 0) sc = 0;
    __syncthreads();
    unsigned a = dil3d(g_pf, i) & g_pk[i];
    int cnt = __popc(a);
    #pragma unroll
    for (int off = 16; off > 0; off >>= 1) cnt += __shfl_down_sync(0xffffffffu, cnt, off);
    if ((threadIdx.x & 31) == 0 && cnt) atomicAdd(&sc, cnt);
    g_pa[i] = a & ~g_pf[i];
    __syncthreads();
    if (threadIdx.x == 0 && sc) atomicAdd(&g_bp[i >> 16], sc);
}

// union = feat_kept | padding_even; empty-batch fix bit applied virtually
__global__ void k_unionw(){
    int i = blockIdx.x*256 + threadIdx.x;
    int t = i >> 2;
    int y = t & (DD-1);
    int z = (t >> 7) & (DD-1);
    int b = i >> 16;
    unsigned pe = 0;
    if (!(y & 1) && !(z & 1)){
        int fixw = (g_bp[b] == 0) ? (b*WPB + 127*ROWW + 127*NW + 3) : -1;
        auto L = [&](int j) -> unsigned {
            unsigned v = g_pa[j];
            if (j == fixw) v |= 0x80000000u;
            return v;
        };
        unsigned q = L(i) | L(i+NW) | L(i+ROWW) | L(i+ROWW+NW);
        pe = (q | (q >> 1)) & 0x55555555u;
    }
    g_pb[i] = g_pf[i] | pe;
}

// mask = dil3d(union), unpacked to floats
__global__ void k_dmask(float* __restrict__ out){
    int i = blockIdx.x*256 + threadIdx.x;
    unsigned r = dil3d(g_pb, i);
    float4* o = (float4*)(out + MASK_OFF + (size_t)i*32);
    #pragma unroll
    for (int j = 0; j < 8; j++){
        o[j] = make_float4((r>>(4*j))&1 ? 1.f:0.f, (r>>(4*j+1))&1 ? 1.f:0.f,
                           (r>>(4*j+2))&1 ? 1.f:0.f, (r>>(4*j+3))&1 ? 1.f:0.f);
    }
}

// ---------------- launch ----------------
extern "C" void kernel_launch(void* const* d_in, const int* in_sizes, int n_in,
                              void* d_out, int out_size){
    const float* sem   = (const float*)d_in[0];
    const float* depth = (const float*)d_in[1];
    const float* occ   = (const float*)d_in[2];
    const unsigned int* kept = (const unsigned int*)d_in[3];
    const float4* mapping = (const float4*)d_in[4];
    float* out = (float*)d_out;

    const int WG = NWORDS/256;  // 512
    k_front <<<BN, 1024>>>(sem, depth);
    k_feat  <<<dim3(30, 5, BN*15), dim3(160, 2)>>>(occ, out);
    k_voxel <<<NVOXB/256, 256>>>(mapping, kept, out);
    k_dpk   <<<WG, 256>>>();
    k_unionw<<<WG, 256>>>();
    k_dmask <<<WG, 256>>>(out);
}

// round 6
// speedup vs baseline: 1.3083x; 1.3083x over previous
#include <cuda_runtime.h>
#include <math.h>

#define BN 2
#define KC 12
#define HH 120
#define WW 160
#define HW (HH*WW)          // 19200
#define NB 100
#define DD 128
#define NVOX (DD*DD*DD)
#define NVOXB (BN*NVOX)     // 4194304
#define NW 4                // 32-bit words per x-row
#define ROWW (NW*DD)        // word stride per z-slice = 512
#define NWORDS (NVOXB/32)   // 131072
#define WPB 65536           // words per batch
#define FEAT_ELEMS (BN*15*NB*HW)
#define FK_OFF FEAT_ELEMS
#define MASK_OFF (FEAT_ELEMS + NVOXB)

// ---------------- scratch (device globals; no allocations) ----------------
__device__ float          g_sm[BN*KC*HW];   // softmax features
__device__ int            g_di[BN*HW];      // depth_index
__device__ unsigned char  g_sind[BN*HW];    // sem>=10 indicator
__device__ float          g_sd[BN*HW];      // clamped depth -> stuff_depth
__device__ float          g_sx[BN*WW];
__device__ float          g_sy[BN*HH];
__device__ unsigned int   g_pf[NWORDS];     // packed feat_kept
__device__ unsigned int   g_pk[NWORDS];     // packed kept
__device__ unsigned int   g_pa[NWORDS];     // packed padding_kept
__device__ unsigned int   g_pb[NWORDS];     // packed union
__device__ int            g_bp[BN];

// ---------------- stage 1: per-pixel softmax/argmax/depth (chip-wide) ----------------
__global__ void k_pix(const float* __restrict__ sem, const float* __restrict__ depth){
    int i = blockIdx.x*blockDim.x + threadIdx.x;
    if (i == 0){ g_bp[0] = 0; g_bp[1] = 0; }
    if (i >= BN*HW) return;
    int b = i / HW, p = i - b*HW;
    const float* s = sem + (size_t)b*KC*HW + p;
    float v[KC]; float mx = -1e30f; int am = 0;
    #pragma unroll
    for (int k = 0; k < KC; k++){ v[k] = s[(size_t)k*HW]; if (v[k] > mx){ mx = v[k]; am = k; } }
    float sum = 0.f;
    #pragma unroll
    for (int k = 0; k < KC; k++){ v[k] = expf(v[k]-mx); sum += v[k]; }
    float inv = 1.f/sum;
    float* o = g_sm + (size_t)b*KC*HW + p;
    #pragma unroll
    for (int k = 0; k < KC; k++) o[(size_t)k*HW] = v[k]*inv;
    g_sind[i] = (unsigned char)(am >= 10);
    float dc = fminf(depth[i], 6.f);
    g_di[i] = (int)(dc/6.f*100.f);
    g_sd[i] = dc;
}

// ---------------- stage 2: 5x5 erosion (chip-wide) ----------------
__global__ void k_erode(){
    int i = blockIdx.x*blockDim.x + threadIdx.x;
    if (i >= BN*HW) return;
    int b = i / HW, p = i - b*HW, h = p / WW, w = p - h*WW;
    bool all1 = true;
    #pragma unroll
    for (int dh = -2; dh <= 2; dh++){
        int h2 = h + dh; if (h2 < 0 || h2 >= HH) continue;
        #pragma unroll
        for (int dw = -2; dw <= 2; dw++){
            int w2 = w + dw; if (w2 < 0 || w2 >= WW) continue;
            if (!g_sind[b*HW + h2*WW + w2]) all1 = false;
        }
    }
    if (!all1) g_sd[i] = 0.f;
}

// ---------------- stage 3: border padding + axis maxes + find_none (per batch) ----------------
__device__ void find_none_dev(const float* a, int n, float* out){
    float suf[WW];
    float run = INFINITY;
    for (int ii = n-1; ii >= 0; ii--){
        suf[ii] = run;
        float av = (a[ii] != 0.f) ? a[ii] : INFINITY;
        run = fminf(run, av);
    }
    float m = INFINITY;
    for (int ii = 0; ii < n; ii++){
        float l = isinf(m)      ? 0.f : m;
        float r = isinf(suf[ii])? 0.f : suf[ii];
        float val = (a[ii] == 0.f) ? fmaxf(l, r) : a[ii];
        if (val != 0.f) m = fminf(m, val);
        out[ii] = val;
    }
}

__global__ void k_small(){
    __shared__ float ymax[HH], xmax[WW], colm[WW], rowm[HH];
    __shared__ float vy, vyr, vx, vxr;
    int b = blockIdx.x, tid = threadIdx.x;
    const float* sd = g_sd + b*HW;
    for (int h = tid; h < HH; h += blockDim.x){
        float m = 0.f; for (int w = 0; w < WW; w++) m = fmaxf(m, sd[h*WW+w]); ymax[h] = m;
    }
    for (int w = tid; w < WW; w += blockDim.x){
        float m = 0.f; for (int h = 0; h < HH; h++) m = fmaxf(m, sd[h*WW+w]); xmax[w] = m;
    }
    __syncthreads();
    if (tid == 0){
        float a = 0.f; for (int h = 0; h < HH; h++)      if (ymax[h] != 0.f){ a = ymax[h]; break; } vy  = a;
        a = 0.f;       for (int h = HH-1; h >= 0; h--)   if (ymax[h] != 0.f){ a = ymax[h]; break; } vyr = a;
        a = 0.f;       for (int w = 0; w < WW; w++)      if (xmax[w] != 0.f){ a = xmax[w]; break; } vx  = a;
        a = 0.f;       for (int w = WW-1; w >= 0; w--)   if (xmax[w] != 0.f){ a = xmax[w]; break; } vxr = a;
    }
    __syncthreads();
    auto sdval = [&](int h, int w) -> float {
        float v = sd[h*WW + w];
        if (w == 0)      return (v != 0.f) ? v : vx;
        if (w == WW-1)   return (v != 0.f) ? v : vxr;
        if (h == 0)      return (v != 0.f) ? v : vy;
        if (h == HH-1)   return (v != 0.f) ? v : vyr;
        return v;
    };
    for (int w = tid; w < WW; w += blockDim.x){
        float m = 0.f; for (int h = 0; h < HH; h++) m = fmaxf(m, sdval(h, w)); colm[w] = m;
    }
    for (int h = tid; h < HH; h += blockDim.x){
        float m = 0.f; for (int w = 0; w < WW; w++) m = fmaxf(m, sdval(h, w)); rowm[h] = m;
    }
    __syncthreads();
    if (tid == 0)  find_none_dev(colm, WW, g_sx + b*WW);
    if (tid == 32) find_none_dev(rowm, HH, g_sy + b*HH);
}

// ---------------- stage 4: features (block (160,2), 10 d-bins per thread) ----------------
__global__ void k_feat(const float* __restrict__ occ, float* __restrict__ out){
    int p4 = blockIdx.x*160 + threadIdx.x;           // 0..4799
    int d0 = blockIdx.y*20 + threadIdx.y*10;         // 0..90 step 10
    int cz = blockIdx.z; int b = cz/15, c = cz - b*15;
    float4* ob = (float4*)out + (size_t)cz*NB*(HW/4) + p4;
    if (c < KC){
        float4 o = ((const float4*)g_sm)[(size_t)(b*KC + c)*(HW/4) + p4];
        #pragma unroll
        for (int q = 0; q < 10; q++)
            ob[(size_t)(d0+q)*(HW/4)] = o;
    } else if (c == 13){
        const int4 di4 = ((const int4*)g_di)[b*(HW/4) + p4];
        #pragma unroll
        for (int q = 0; q < 10; q++){
            int d = d0 + q;
            float4 o;
            o.x = (d > di4.x) ? 1.f : ((d < di4.x) ? -1.f : 0.f);
            o.y = (d > di4.y) ? 1.f : ((d < di4.y) ? -1.f : 0.f);
            o.z = (d > di4.z) ? 1.f : ((d < di4.z) ? -1.f : 0.f);
            o.w = (d > di4.w) ? 1.f : ((d < di4.w) ? -1.f : 0.f);
            ob[(size_t)d*(HW/4)] = o;
        }
    } else if (c == 14){
        const int4 di4 = ((const int4*)g_di)[b*(HW/4) + p4];
        #pragma unroll
        for (int q = 0; q < 10; q++){
            int d = d0 + q;
            float4 o;
            o.x = fabsf((float)(d - di4.x)*0.06f);
            o.y = fabsf((float)(d - di4.y)*0.06f);
            o.z = fabsf((float)(d - di4.z)*0.06f);
            o.w = fabsf((float)(d - di4.w)*0.06f);
            ob[(size_t)d*(HW/4)] = o;
        }
    } else { // c == 12 : depth_weight
        int h = p4/40, w0 = (p4 - h*40)*4;
        float sy = g_sy[b*HH + h];
        const int4 di4 = ((const int4*)g_di)[b*(HW/4) + p4];
        int di[4] = {di4.x, di4.y, di4.z, di4.w};
        int dmb[4];
        #pragma unroll
        for (int l = 0; l < 4; l++)
            dmb[l] = (int)(fminf(g_sx[b*WW + w0 + l], sy)/6.f*100.f);
        const float4* occ4 = (const float4*)occ + (size_t)b*NB*(HW/4) + p4;
        #pragma unroll
        for (int q = 0; q < 10; q++){
            int d = d0 + q;
            float4 ov = occ4[(size_t)d*(HW/4)];
            float ovv[4] = {ov.x, ov.y, ov.z, ov.w};
            float res[4];
            #pragma unroll
            for (int l = 0; l < 4; l++){
                bool kp = (d > di[l] - 3) && (d < dmb[l] + 5);
                res[l] = kp ? (1.f/(1.f + expf(-ovv[l]))) : 0.f;
            }
            ob[(size_t)d*(HW/4)] = make_float4(res[0], res[1], res[2], res[3]);
        }
    }
}

// ---------------- stage 5: voxel gather -> feat_kept (predicated + ballot pack) ----------------
__global__ void k_voxel(const float4* __restrict__ mapping,
                        const unsigned int* __restrict__ kept,
                        float* __restrict__ out){
    int v = blockIdx.x*blockDim.x + threadIdx.x;
    bool kp = (kept[v] != 0u);
    bool fk = false;
    if (kp){
        float4 m = mapping[v];
        int b = (int)m.x, x = (int)m.y, y = (int)m.z;
        int didx = (int)(m.w*100.f/6.f);
        int di  = g_di[b*HW + y*WW + x];
        int dmb = (int)(fminf(g_sx[b*WW + x], g_sy[b*HH + y])/6.f*100.f);
        fk = (didx > di - 3) && (didx < dmb + 5);
    }
    unsigned bf = __ballot_sync(0xffffffffu, fk);
    unsigned bk = __ballot_sync(0xffffffffu, kp);
    if ((threadIdx.x & 31) == 0){
        g_pf[v >> 5] = bf;
        g_pk[v >> 5] = bk;
    }
    out[FK_OFF + v] = fk ? 1.f : 0.f;
}

// ---------------- fused packed 5^3 dilation: (z,y) word ORs + x via shuffles ----------------
__device__ __forceinline__ unsigned dil3d(const unsigned int* in, int i){
    int t = i >> 2;
    int y = t & (DD-1);
    int z = (t >> 7) & (DD-1);
    unsigned zy = 0;
    #pragma unroll
    for (int dz = -2; dz <= 2; dz++){
        int zz = z + dz; if (zz < 0 || zz >= DD) continue;
        #pragma unroll
        for (int dy = -2; dy <= 2; dy++){
            int yy = y + dy; if (yy < 0 || yy >= DD) continue;
            zy |= in[i + (dz*DD + dy)*NW];
        }
    }
    // x-dilation: an x-row is NW=4 consecutive words, aligned to 4-lane groups
    int wx = i & (NW-1);
    unsigned p = __shfl_up_sync(0xffffffffu, zy, 1);
    unsigned n = __shfl_down_sync(0xffffffffu, zy, 1);
    if (wx == 0)    p = 0u;
    if (wx == NW-1) n = 0u;
    return zy | (zy<<1) | (zy<<2) | (zy>>1) | (zy>>2)
              | (p>>31) | (p>>30) | (n<<31) | (n<<30);
}

// padding_kept = dil3d(feat_kept) & kept; popcount -> g_bp; &= ~feat_kept
__global__ void k_dpk(){
    __shared__ int sc;
    int i = blockIdx.x*256 + threadIdx.x;
    if (threadIdx.x == 0) sc = 0;
    __syncthreads();
    unsigned a = dil3d(g_pf, i) & g_pk[i];
    int cnt = __popc(a);
    #pragma unroll
    for (int off = 16; off > 0; off >>= 1) cnt += __shfl_down_sync(0xffffffffu, cnt, off);
    if ((threadIdx.x & 31) == 0 && cnt) atomicAdd(&sc, cnt);
    g_pa[i] = a & ~g_pf[i];
    __syncthreads();
    if (threadIdx.x == 0 && sc) atomicAdd(&g_bp[i >> 16], sc);
}

// union = feat_kept | padding_even; empty-batch fix bit applied virtually
__global__ void k_unionw(){
    int i = blockIdx.x*256 + threadIdx.x;
    int t = i >> 2;
    int y = t & (DD-1);
    int z = (t >> 7) & (DD-1);
    int b = i >> 16;
    unsigned pe = 0;
    if (!(y & 1) && !(z & 1)){
        int fixw = (g_bp[b] == 0) ? (b*WPB + 127*ROWW + 127*NW + 3) : -1;
        auto L = [&](int j) -> unsigned {
            unsigned v = g_pa[j];
            if (j == fixw) v |= 0x80000000u;
            return v;
        };
        unsigned q = L(i) | L(i+NW) | L(i+ROWW) | L(i+ROWW+NW);
        pe = (q | (q >> 1)) & 0x55555555u;
    }
    g_pb[i] = g_pf[i] | pe;
}

// mask = dil3d(union), unpacked to floats
__global__ void k_dmask(float* __restrict__ out){
    int i = blockIdx.x*256 + threadIdx.x;
    unsigned r = dil3d(g_pb, i);
    float4* o = (float4*)(out + MASK_OFF + (size_t)i*32);
    #pragma unroll
    for (int j = 0; j < 8; j++){
        o[j] = make_float4((r>>(4*j))&1 ? 1.f:0.f, (r>>(4*j+1))&1 ? 1.f:0.f,
                           (r>>(4*j+2))&1 ? 1.f:0.f, (r>>(4*j+3))&1 ? 1.f:0.f);
    }
}

// ---------------- launch ----------------
extern "C" void kernel_launch(void* const* d_in, const int* in_sizes, int n_in,
                              void* d_out, int out_size){
    const float* sem   = (const float*)d_in[0];
    const float* depth = (const float*)d_in[1];
    const float* occ   = (const float*)d_in[2];
    const unsigned int* kept = (const unsigned int*)d_in[3];
    const float4* mapping = (const float4*)d_in[4];
    float* out = (float*)d_out;

    const int T = 256;
    const int WG = NWORDS/256;  // 512
    k_pix   <<<(BN*HW + T-1)/T, T>>>(sem, depth);
    k_erode <<<(BN*HW + T-1)/T, T>>>();
    k_small <<<BN, 256>>>();
    k_feat  <<<dim3(30, 5, BN*15), dim3(160, 2)>>>(occ, out);
    k_voxel <<<NVOXB/T, T>>>(mapping, kept, out);
    k_dpk   <<<WG, T>>>();
    k_unionw<<<WG, T>>>();
    k_dmask <<<WG, T>>>(out);
}

// round 7
// speedup vs baseline: 1.3647x; 1.0431x over previous
#include <cuda_runtime.h>
#include <math.h>

#define BN 2
#define KC 12
#define HH 120
#define WW 160
#define HW (HH*WW)          // 19200
#define NB 100
#define DD 128
#define NVOX (DD*DD*DD)
#define NVOXB (BN*NVOX)     // 4194304
#define NW 4                // 32-bit words per x-row
#define ROWW (NW*DD)        // word stride per z-slice = 512
#define NWORDS (NVOXB/32)   // 131072
#define WPB 65536           // words per batch
#define FEAT_ELEMS (BN*15*NB*HW)
#define FK_OFF FEAT_ELEMS
#define MASK_OFF (FEAT_ELEMS + NVOXB)

// voxel work appended to k_feat grid: z slices [30, 30+VZ)
#define VZ 88               // 88*150 blocks * 320 thr = 4,224,000 >= NVOXB

// ---------------- scratch (device globals; no allocations) ----------------
__device__ float          g_sm[BN*KC*HW];   // softmax features
__device__ int            g_di[BN*HW];      // depth_index
__device__ unsigned char  g_sind[BN*HW];    // sem>=10 indicator
__device__ float          g_sd[BN*HW];      // clamped depth -> stuff_depth
__device__ float          g_sx[BN*WW];
__device__ float          g_sy[BN*HH];
__device__ unsigned int   g_pf[NWORDS];     // packed feat_kept
__device__ unsigned int   g_pk[NWORDS];     // packed kept
__device__ unsigned int   g_pa[NWORDS];     // packed padding_kept
__device__ unsigned int   g_pb[NWORDS];     // packed union
__device__ int            g_bp[BN];

// ---------------- stage 1: per-pixel softmax/argmax/depth (chip-wide) ----------------
__global__ void k_pix(const float* __restrict__ sem, const float* __restrict__ depth){
    int i = blockIdx.x*blockDim.x + threadIdx.x;
    if (i == 0){ g_bp[0] = 0; g_bp[1] = 0; }
    if (i >= BN*HW) return;
    int b = i / HW, p = i - b*HW;
    const float* s = sem + (size_t)b*KC*HW + p;
    float v[KC]; float mx = -1e30f; int am = 0;
    #pragma unroll
    for (int k = 0; k < KC; k++){ v[k] = s[(size_t)k*HW]; if (v[k] > mx){ mx = v[k]; am = k; } }
    float sum = 0.f;
    #pragma unroll
    for (int k = 0; k < KC; k++){ v[k] = expf(v[k]-mx); sum += v[k]; }
    float inv = 1.f/sum;
    float* o = g_sm + (size_t)b*KC*HW + p;
    #pragma unroll
    for (int k = 0; k < KC; k++) o[(size_t)k*HW] = v[k]*inv;
    g_sind[i] = (unsigned char)(am >= 10);
    float dc = fminf(depth[i], 6.f);
    g_di[i] = (int)(dc/6.f*100.f);
    g_sd[i] = dc;
}

// ---------------- stage 2: 5x5 erosion (chip-wide) ----------------
__global__ void k_erode(){
    int i = blockIdx.x*blockDim.x + threadIdx.x;
    if (i >= BN*HW) return;
    int b = i / HW, p = i - b*HW, h = p / WW, w = p - h*WW;
    bool all1 = true;
    #pragma unroll
    for (int dh = -2; dh <= 2; dh++){
        int h2 = h + dh; if (h2 < 0 || h2 >= HH) continue;
        #pragma unroll
        for (int dw = -2; dw <= 2; dw++){
            int w2 = w + dw; if (w2 < 0 || w2 >= WW) continue;
            if (!g_sind[b*HW + h2*WW + w2]) all1 = false;
        }
    }
    if (!all1) g_sd[i] = 0.f;
}

// ---------------- stage 3: border padding + axis maxes + find_none (per batch) ----------------
__device__ void find_none_dev(const float* a, int n, float* out){
    float suf[WW];
    float run = INFINITY;
    for (int ii = n-1; ii >= 0; ii--){
        suf[ii] = run;
        float av = (a[ii] != 0.f) ? a[ii] : INFINITY;
        run = fminf(run, av);
    }
    float m = INFINITY;
    for (int ii = 0; ii < n; ii++){
        float l = isinf(m)      ? 0.f : m;
        float r = isinf(suf[ii])? 0.f : suf[ii];
        float val = (a[ii] == 0.f) ? fmaxf(l, r) : a[ii];
        if (val != 0.f) m = fminf(m, val);
        out[ii] = val;
    }
}

__global__ void k_small(){
    __shared__ float ymax[HH], xmax[WW], colm[WW], rowm[HH];
    __shared__ float vy, vyr, vx, vxr;
    int b = blockIdx.x, tid = threadIdx.x;
    const float* sd = g_sd + b*HW;
    for (int h = tid; h < HH; h += blockDim.x){
        float m = 0.f; for (int w = 0; w < WW; w++) m = fmaxf(m, sd[h*WW+w]); ymax[h] = m;
    }
    for (int w = tid; w < WW; w += blockDim.x){
        float m = 0.f; for (int h = 0; h < HH; h++) m = fmaxf(m, sd[h*WW+w]); xmax[w] = m;
    }
    __syncthreads();
    if (tid == 0){
        float a = 0.f; for (int h = 0; h < HH; h++)      if (ymax[h] != 0.f){ a = ymax[h]; break; } vy  = a;
        a = 0.f;       for (int h = HH-1; h >= 0; h--)   if (ymax[h] != 0.f){ a = ymax[h]; break; } vyr = a;
        a = 0.f;       for (int w = 0; w < WW; w++)      if (xmax[w] != 0.f){ a = xmax[w]; break; } vx  = a;
        a = 0.f;       for (int w = WW-1; w >= 0; w--)   if (xmax[w] != 0.f){ a = xmax[w]; break; } vxr = a;
    }
    __syncthreads();
    auto sdval = [&](int h, int w) -> float {
        float v = sd[h*WW + w];
        if (w == 0)      return (v != 0.f) ? v : vx;
        if (w == WW-1)   return (v != 0.f) ? v : vxr;
        if (h == 0)      return (v != 0.f) ? v : vy;
        if (h == HH-1)   return (v != 0.f) ? v : vyr;
        return v;
    };
    for (int w = tid; w < WW; w += blockDim.x){
        float m = 0.f; for (int h = 0; h < HH; h++) m = fmaxf(m, sdval(h, w)); colm[w] = m;
    }
    for (int h = tid; h < HH; h += blockDim.x){
        float m = 0.f; for (int w = 0; w < WW; w++) m = fmaxf(m, sdval(h, w)); rowm[h] = m;
    }
    __syncthreads();
    if (tid == 0)  find_none_dev(colm, WW, g_sx + b*WW);
    if (tid == 32) find_none_dev(rowm, HH, g_sy + b*HH);
}

// ---------------- stage 4: fused features + voxel gather ----------------
// z in [0,30): feature channels, 10 d-bins per thread.
// z in [30,30+VZ): voxel gather (feat_kept) with linearized block index.
__global__ void __launch_bounds__(320, 6)
k_feat(const float* __restrict__ occ,
       const float4* __restrict__ mapping,
       const unsigned int* __restrict__ kept,
       float* __restrict__ out){
    if (blockIdx.z >= 30){
        // ---- voxel path ----
        int lb  = (blockIdx.z - 30)*150 + blockIdx.y*30 + blockIdx.x;
        int tid = threadIdx.y*160 + threadIdx.x;
        int v   = lb*320 + tid;
        if (v >= NVOXB) return;            // whole warps only (boundary is 32-aligned)
        bool kp = (kept[v] != 0u);
        bool fk = false;
        if (kp){
            float4 m = mapping[v];
            int b = (int)m.x, x = (int)m.y, y = (int)m.z;
            int didx = (int)(m.w*100.f/6.f);
            int di  = g_di[b*HW + y*WW + x];
            int dmb = (int)(fminf(g_sx[b*WW + x], g_sy[b*HH + y])/6.f*100.f);
            fk = (didx > di - 3) && (didx < dmb + 5);
        }
        unsigned bf = __ballot_sync(0xffffffffu, fk);
        unsigned bk = __ballot_sync(0xffffffffu, kp);
        if ((tid & 31) == 0){
            g_pf[v >> 5] = bf;
            g_pk[v >> 5] = bk;
        }
        out[FK_OFF + v] = fk ? 1.f : 0.f;
        return;
    }
    // ---- feature path ----
    int p4 = blockIdx.x*160 + threadIdx.x;           // 0..4799
    int d0 = blockIdx.y*20 + threadIdx.y*10;         // 0..90 step 10
    int cz = blockIdx.z; int b = cz/15, c = cz - b*15;
    float4* ob = (float4*)out + (size_t)cz*NB*(HW/4) + p4;
    if (c < KC){
        float4 o = ((const float4*)g_sm)[(size_t)(b*KC + c)*(HW/4) + p4];
        #pragma unroll
        for (int q = 0; q < 10; q++)
            ob[(size_t)(d0+q)*(HW/4)] = o;
    } else if (c == 13){
        const int4 di4 = ((const int4*)g_di)[b*(HW/4) + p4];
        #pragma unroll
        for (int q = 0; q < 10; q++){
            int d = d0 + q;
            float4 o;
            o.x = (d > di4.x) ? 1.f : ((d < di4.x) ? -1.f : 0.f);
            o.y = (d > di4.y) ? 1.f : ((d < di4.y) ? -1.f : 0.f);
            o.z = (d > di4.z) ? 1.f : ((d < di4.z) ? -1.f : 0.f);
            o.w = (d > di4.w) ? 1.f : ((d < di4.w) ? -1.f : 0.f);
            ob[(size_t)d*(HW/4)] = o;
        }
    } else if (c == 14){
        const int4 di4 = ((const int4*)g_di)[b*(HW/4) + p4];
        #pragma unroll
        for (int q = 0; q < 10; q++){
            int d = d0 + q;
            float4 o;
            o.x = fabsf((float)(d - di4.x)*0.06f);
            o.y = fabsf((float)(d - di4.y)*0.06f);
            o.z = fabsf((float)(d - di4.z)*0.06f);
            o.w = fabsf((float)(d - di4.w)*0.06f);
            ob[(size_t)d*(HW/4)] = o;
        }
    } else { // c == 12 : depth_weight
        int h = p4/40, w0 = (p4 - h*40)*4;
        float sy = g_sy[b*HH + h];
        const int4 di4 = ((const int4*)g_di)[b*(HW/4) + p4];
        int di[4] = {di4.x, di4.y, di4.z, di4.w};
        int dmb[4];
        #pragma unroll
        for (int l = 0; l < 4; l++)
            dmb[l] = (int)(fminf(g_sx[b*WW + w0 + l], sy)/6.f*100.f);
        const float4* occ4 = (const float4*)occ + (size_t)b*NB*(HW/4) + p4;
        #pragma unroll
        for (int q = 0; q < 10; q++){
            int d = d0 + q;
            float4 ov = occ4[(size_t)d*(HW/4)];
            float ovv[4] = {ov.x, ov.y, ov.z, ov.w};
            float res[4];
            #pragma unroll
            for (int l = 0; l < 4; l++){
                bool kp = (d > di[l] - 3) && (d < dmb[l] + 5);
                res[l] = kp ? (1.f/(1.f + expf(-ovv[l]))) : 0.f;
            }
            ob[(size_t)d*(HW/4)] = make_float4(res[0], res[1], res[2], res[3]);
        }
    }
}

// ---------------- fused packed 5^3 dilation: (z,y) word ORs + x via shuffles ----------------
__device__ __forceinline__ unsigned dil3d(const unsigned int* in, int i){
    int t = i >> 2;
    int y = t & (DD-1);
    int z = (t >> 7) & (DD-1);
    unsigned zy = 0;
    #pragma unroll
    for (int dz = -2; dz <= 2; dz++){
        int zz = z + dz; if (zz < 0 || zz >= DD) continue;
        #pragma unroll
        for (int dy = -2; dy <= 2; dy++){
            int yy = y + dy; if (yy < 0 || yy >= DD) continue;
            zy |= in[i + (dz*DD + dy)*NW];
        }
    }
    int wx = i & (NW-1);
    unsigned p = __shfl_up_sync(0xffffffffu, zy, 1);
    unsigned n = __shfl_down_sync(0xffffffffu, zy, 1);
    if (wx == 0)    p = 0u;
    if (wx == NW-1) n = 0u;
    return zy | (zy<<1) | (zy<<2) | (zy>>1) | (zy>>2)
              | (p>>31) | (p>>30) | (n<<31) | (n<<30);
}

// padding_kept = dil3d(feat_kept) & kept; popcount -> g_bp; &= ~feat_kept
__global__ void k_dpk(){
    __shared__ int sc;
    int i = blockIdx.x*256 + threadIdx.x;
    if (threadIdx.x == 0) sc = 0;
    __syncthreads();
    unsigned a = dil3d(g_pf, i) & g_pk[i];
    int cnt = __popc(a);
    #pragma unroll
    for (int off = 16; off > 0; off >>= 1) cnt += __shfl_down_sync(0xffffffffu, cnt, off);
    if ((threadIdx.x & 31) == 0 && cnt) atomicAdd(&sc, cnt);
    g_pa[i] = a & ~g_pf[i];
    __syncthreads();
    if (threadIdx.x == 0 && sc) atomicAdd(&g_bp[i >> 16], sc);
}

// union = feat_kept | padding_even; empty-batch fix bit applied virtually
__global__ void k_unionw(){
    int i = blockIdx.x*256 + threadIdx.x;
    int t = i >> 2;
    int y = t & (DD-1);
    int z = (t >> 7) & (DD-1);
    int b = i >> 16;
    unsigned pe = 0;
    if (!(y & 1) && !(z & 1)){
        int fixw = (g_bp[b] == 0) ? (b*WPB + 127*ROWW + 127*NW + 3) : -1;
        auto L = [&](int j) -> unsigned {
            unsigned v = g_pa[j];
            if (j == fixw) v |= 0x80000000u;
            return v;
        };
        unsigned q = L(i) | L(i+NW) | L(i+ROWW) | L(i+ROWW+NW);
        pe = (q | (q >> 1)) & 0x55555555u;
    }
    g_pb[i] = g_pf[i] | pe;
}

// mask = dil3d(union), unpacked to floats
__global__ void k_dmask(float* __restrict__ out){
    int i = blockIdx.x*256 + threadIdx.x;
    unsigned r = dil3d(g_pb, i);
    float4* o = (float4*)(out + MASK_OFF + (size_t)i*32);
    #pragma unroll
    for (int j = 0; j < 8; j++){
        o[j] = make_float4((r>>(4*j))&1 ? 1.f:0.f, (r>>(4*j+1))&1 ? 1.f:0.f,
                           (r>>(4*j+2))&1 ? 1.f:0.f, (r>>(4*j+3))&1 ? 1.f:0.f);
    }
}

// ---------------- launch ----------------
extern "C" void kernel_launch(void* const* d_in, const int* in_sizes, int n_in,
                              void* d_out, int out_size){
    const float* sem   = (const float*)d_in[0];
    const float* depth = (const float*)d_in[1];
    const float* occ   = (const float*)d_in[2];
    const unsigned int* kept = (const unsigned int*)d_in[3];
    const float4* mapping = (const float4*)d_in[4];
    float* out = (float*)d_out;

    const int T = 256;
    const int WG = NWORDS/256;  // 512
    k_pix   <<<(BN*HW + T-1)/T, T>>>(sem, depth);
    k_erode <<<(BN*HW + T-1)/T, T>>>();
    k_small <<<BN, 256>>>();
    k_feat  <<<dim3(30, 5, 30 + VZ), dim3(160, 2)>>>(occ, mapping, kept, out);
    k_dpk   <<<WG, T>>>();
    k_unionw<<<WG, T>>>();
    k_dmask <<<WG, T>>>(out);
}

// round 8
// speedup vs baseline: 1.5592x; 1.1425x over previous
#include <cuda_runtime.h>
#include <math.h>

#define BN 2
#define KC 12
#define HH 120
#define WW 160
#define HW (HH*WW)          // 19200
#define NB 100
#define DD 128
#define NVOX (DD*DD*DD)
#define NVOXB (BN*NVOX)     // 4194304
#define NW 4                // 32-bit words per x-row
#define ROWW (NW*DD)        // word stride per z-slice = 512
#define NWORDS (NVOXB/32)   // 131072
#define WPB 65536           // words per batch
#define FEAT_ELEMS (BN*15*NB*HW)
#define FK_OFF FEAT_ELEMS
#define MASK_OFF (FEAT_ELEMS + NVOXB)

// voxel work appended to k_feat grid: z slices [30, 30+VZ)
#define VZ 88               // 88*150 blocks * 320 thr = 4,224,000 >= NVOXB

// ---------------- scratch (device globals; no allocations) ----------------
__device__ float          g_sm[BN*KC*HW];   // softmax features
__device__ int            g_di[BN*HW];      // depth_index
__device__ unsigned char  g_sind[BN*HW];    // sem>=10 indicator
__device__ float          g_sd[BN*HW];      // clamped depth
__device__ float          g_sx[BN*WW];
__device__ float          g_sy[BN*HH];
__device__ unsigned int   g_pf[NWORDS];     // packed feat_kept
__device__ unsigned int   g_pk[NWORDS];     // packed kept
__device__ unsigned int   g_pa[NWORDS];     // packed padding_kept
__device__ int            g_bp[BN];

// ---------------- stage 1: per-pixel softmax/argmax/depth (chip-wide) ----------------
__global__ void k_pix(const float* __restrict__ sem, const float* __restrict__ depth){
    int i = blockIdx.x*blockDim.x + threadIdx.x;
    if (i == 0){ g_bp[0] = 0; g_bp[1] = 0; }
    if (i >= BN*HW) return;
    int b = i / HW, p = i - b*HW;
    const float* s = sem + (size_t)b*KC*HW + p;
    float v[KC]; float mx = -1e30f; int am = 0;
    #pragma unroll
    for (int k = 0; k < KC; k++){ v[k] = s[(size_t)k*HW]; if (v[k] > mx){ mx = v[k]; am = k; } }
    float sum = 0.f;
    #pragma unroll
    for (int k = 0; k < KC; k++){ v[k] = expf(v[k]-mx); sum += v[k]; }
    float inv = 1.f/sum;
    float* o = g_sm + (size_t)b*KC*HW + p;
    #pragma unroll
    for (int k = 0; k < KC; k++) o[(size_t)k*HW] = v[k]*inv;
    g_sind[i] = (unsigned char)(am >= 10);
    float dc = fminf(depth[i], 6.f);
    g_di[i] = (int)(dc/6.f*100.f);
    g_sd[i] = dc;
}

// ---------------- stage 2: fused erosion + axis maxes + find_none (smem) ----------------
__device__ void find_none_dev(const float* a, int n, float* out){
    float suf[WW];
    float run = INFINITY;
    for (int ii = n-1; ii >= 0; ii--){
        suf[ii] = run;
        float av = (a[ii] != 0.f) ? a[ii] : INFINITY;
        run = fminf(run, av);
    }
    float m = INFINITY;
    for (int ii = 0; ii < n; ii++){
        float l = isinf(m)      ? 0.f : m;
        float r = isinf(suf[ii])? 0.f : suf[ii];
        float val = (a[ii] == 0.f) ? fmaxf(l, r) : a[ii];
        if (val != 0.f) m = fminf(m, val);
        out[ii] = val;
    }
}

// dynamic smem: s_sd[HW] f32 | s_si[HW] u8 | s_rm[HW] u8 | ymax[HH] | xmax[WW] | colm[WW] | rowm[HH] | 4 scalars
#define SM2_BYTES (HW*4 + HW + HW + (HH+WW+WW+HH)*4 + 16)

__global__ void k_small(){
    extern __shared__ unsigned char smraw[];
    float*         s_sd = (float*)smraw;
    unsigned char* s_si = (unsigned char*)(s_sd + HW);
    unsigned char* s_rm = s_si + HW;
    float* ymax = (float*)(s_rm + HW);
    float* xmax = ymax + HH;
    float* colm = xmax + WW;
    float* rowm = colm + WW;
    float* vv   = rowm + HH;     // vy, vyr, vx, vxr

    int b = blockIdx.x, tid = threadIdx.x, nt = blockDim.x;

    // load stuff indicator
    for (int p = tid; p < HW; p += nt) s_si[p] = g_sind[b*HW + p];
    __syncthreads();
    // separable 5x5 erosion: row pass (OOB treated as 1)
    for (int p = tid; p < HW; p += nt){
        int h = p / WW, w = p - h*WW;
        unsigned char m = 1;
        #pragma unroll
        for (int dw = -2; dw <= 2; dw++){
            int w2 = w + dw;
            if (w2 >= 0 && w2 < WW) m &= s_si[h*WW + w2];
        }
        s_rm[p] = m;
    }
    __syncthreads();
    // col pass + build eroded stuff_depth
    for (int p = tid; p < HW; p += nt){
        int h = p / WW;
        unsigned char m = 1;
        #pragma unroll
        for (int dh = -2; dh <= 2; dh++){
            int h2 = h + dh;
            if (h2 >= 0 && h2 < HH) m &= s_rm[h2*WW + (p - h*WW)];
        }
        s_sd[p] = m ? g_sd[b*HW + p] : 0.f;
    }
    __syncthreads();

    // axis maxes
    for (int h = tid; h < HH; h += nt){
        float m = 0.f; for (int w = 0; w < WW; w++) m = fmaxf(m, s_sd[h*WW+w]); ymax[h] = m;
    }
    for (int w = tid; w < WW; w += nt){
        float m = 0.f; for (int h = 0; h < HH; h++) m = fmaxf(m, s_sd[h*WW+w]); xmax[w] = m;
    }
    __syncthreads();
    if (tid == 0){
        float a = 0.f; for (int h = 0; h < HH; h++)      if (ymax[h] != 0.f){ a = ymax[h]; break; } vv[0] = a;
        a = 0.f;       for (int h = HH-1; h >= 0; h--)   if (ymax[h] != 0.f){ a = ymax[h]; break; } vv[1] = a;
        a = 0.f;       for (int w = 0; w < WW; w++)      if (xmax[w] != 0.f){ a = xmax[w]; break; } vv[2] = a;
        a = 0.f;       for (int w = WW-1; w >= 0; w--)   if (xmax[w] != 0.f){ a = xmax[w]; break; } vv[3] = a;
    }
    __syncthreads();
    float vy = vv[0], vyr = vv[1], vx = vv[2], vxr = vv[3];
    // border-padded value; column fills override row fills at corners
    auto sdval = [&](int h, int w) -> float {
        float v = s_sd[h*WW + w];
        if (w == 0)      return (v != 0.f) ? v : vx;
        if (w == WW-1)   return (v != 0.f) ? v : vxr;
        if (h == 0)      return (v != 0.f) ? v : vy;
        if (h == HH-1)   return (v != 0.f) ? v : vyr;
        return v;
    };
    for (int w = tid; w < WW; w += nt){
        float m = 0.f; for (int h = 0; h < HH; h++) m = fmaxf(m, sdval(h, w)); colm[w] = m;
    }
    for (int h = tid; h < HH; h += nt){
        float m = 0.f; for (int w = 0; w < WW; w++) m = fmaxf(m, sdval(h, w)); rowm[h] = m;
    }
    __syncthreads();
    if (tid == 0)  find_none_dev(colm, WW, g_sx + b*WW);
    if (tid == 32) find_none_dev(rowm, HH, g_sy + b*HH);
}

// ---------------- stage 3: fused features + voxel gather ----------------
__global__ void __launch_bounds__(320, 6)
k_feat(const float* __restrict__ occ,
       const float4* __restrict__ mapping,
       const unsigned int* __restrict__ kept,
       float* __restrict__ out){
    if (blockIdx.z >= 30){
        // ---- voxel path ----
        int lb  = (blockIdx.z - 30)*150 + blockIdx.y*30 + blockIdx.x;
        int tid = threadIdx.y*160 + threadIdx.x;
        int v   = lb*320 + tid;
        if (v >= NVOXB) return;            // whole warps only (boundary is 32-aligned)
        bool kp = (kept[v] != 0u);
        bool fk = false;
        if (kp){
            float4 m = __ldcs(&mapping[v]);
            int b = (int)m.x, x = (int)m.y, y = (int)m.z;
            int didx = (int)(m.w*100.f/6.f);
            int di  = g_di[b*HW + y*WW + x];
            int dmb = (int)(fminf(g_sx[b*WW + x], g_sy[b*HH + y])/6.f*100.f);
            fk = (didx > di - 3) && (didx < dmb + 5);
        }
        unsigned bf = __ballot_sync(0xffffffffu, fk);
        unsigned bk = __ballot_sync(0xffffffffu, kp);
        if ((tid & 31) == 0){
            g_pf[v >> 5] = bf;
            g_pk[v >> 5] = bk;
        }
        __stcs(&out[FK_OFF + v], fk ? 1.f : 0.f);
        return;
    }
    // ---- feature path ----
    int p4 = blockIdx.x*160 + threadIdx.x;           // 0..4799
    int d0 = blockIdx.y*20 + threadIdx.y*10;         // 0..90 step 10
    int cz = blockIdx.z; int b = cz/15, c = cz - b*15;
    float4* ob = (float4*)out + (size_t)cz*NB*(HW/4) + p4;
    if (c < KC){
        float4 o = ((const float4*)g_sm)[(size_t)(b*KC + c)*(HW/4) + p4];
        #pragma unroll
        for (int q = 0; q < 10; q++)
            __stcs(&ob[(size_t)(d0+q)*(HW/4)], o);
    } else if (c == 13){
        const int4 di4 = ((const int4*)g_di)[b*(HW/4) + p4];
        #pragma unroll
        for (int q = 0; q < 10; q++){
            int d = d0 + q;
            float4 o;
            o.x = (d > di4.x) ? 1.f : ((d < di4.x) ? -1.f : 0.f);
            o.y = (d > di4.y) ? 1.f : ((d < di4.y) ? -1.f : 0.f);
            o.z = (d > di4.z) ? 1.f : ((d < di4.z) ? -1.f : 0.f);
            o.w = (d > di4.w) ? 1.f : ((d < di4.w) ? -1.f : 0.f);
            __stcs(&ob[(size_t)d*(HW/4)], o);
        }
    } else if (c == 14){
        const int4 di4 = ((const int4*)g_di)[b*(HW/4) + p4];
        #pragma unroll
        for (int q = 0; q < 10; q++){
            int d = d0 + q;
            float4 o;
            o.x = fabsf((float)(d - di4.x)*0.06f);
            o.y = fabsf((float)(d - di4.y)*0.06f);
            o.z = fabsf((float)(d - di4.z)*0.06f);
            o.w = fabsf((float)(d - di4.w)*0.06f);
            __stcs(&ob[(size_t)d*(HW/4)], o);
        }
    } else { // c == 12 : depth_weight
        int h = p4/40, w0 = (p4 - h*40)*4;
        float sy = g_sy[b*HH + h];
        const int4 di4 = ((const int4*)g_di)[b*(HW/4) + p4];
        int di[4] = {di4.x, di4.y, di4.z, di4.w};
        int dmb[4];
        #pragma unroll
        for (int l = 0; l < 4; l++)
            dmb[l] = (int)(fminf(g_sx[b*WW + w0 + l], sy)/6.f*100.f);
        const float4* occ4 = (const float4*)occ + (size_t)b*NB*(HW/4) + p4;
        #pragma unroll
        for (int q = 0; q < 10; q++){
            int d = d0 + q;
            float4 ov = __ldcs(&occ4[(size_t)d*(HW/4)]);
            float ovv[4] = {ov.x, ov.y, ov.z, ov.w};
            float res[4];
            #pragma unroll
            for (int l = 0; l < 4; l++){
                bool kp = (d > di[l] - 3) && (d < dmb[l] + 5);
                res[l] = kp ? (1.f/(1.f + expf(-ovv[l]))) : 0.f;
            }
            __stcs(&ob[(size_t)d*(HW/4)], make_float4(res[0], res[1], res[2], res[3]));
        }
    }
}

// ---------------- fused packed 5^3 dilation: (z,y) word ORs + x via shuffles ----------------
template <typename F>
__device__ __forceinline__ unsigned dil3d_f(F load, int i){
    int t = i >> 2;
    int y = t & (DD-1);
    int z = (t >> 7) & (DD-1);
    unsigned zy = 0;
    #pragma unroll
    for (int dz = -2; dz <= 2; dz++){
        int zz = z + dz; if (zz < 0 || zz >= DD) continue;
        #pragma unroll
        for (int dy = -2; dy <= 2; dy++){
            int yy = y + dy; if (yy < 0 || yy >= DD) continue;
            zy |= load(i + (dz*DD + dy)*NW);
        }
    }
    int wx = i & (NW-1);
    unsigned p = __shfl_up_sync(0xffffffffu, zy, 1);
    unsigned n = __shfl_down_sync(0xffffffffu, zy, 1);
    if (wx == 0)    p = 0u;
    if (wx == NW-1) n = 0u;
    return zy | (zy<<1) | (zy<<2) | (zy>>1) | (zy>>2)
              | (p>>31) | (p>>30) | (n<<31) | (n<<30);
}

// padding_kept = dil3d(feat_kept) & kept; popcount -> g_bp; &= ~feat_kept
__global__ void k_dpk(){
    __shared__ int sc;
    int i = blockIdx.x*256 + threadIdx.x;
    if (threadIdx.x == 0) sc = 0;
    __syncthreads();
    unsigned a = dil3d_f([](int j){ return g_pf[j]; }, i) & g_pk[i];
    int cnt = __popc(a);
    #pragma unroll
    for (int off = 16; off > 0; off >>= 1) cnt += __shfl_down_sync(0xffffffffu, cnt, off);
    if ((threadIdx.x & 31) == 0 && cnt) atomicAdd(&sc, cnt);
    g_pa[i] = a & ~g_pf[i];
    __syncthreads();
    if (threadIdx.x == 0 && sc) atomicAdd(&g_bp[i >> 16], sc);
}

// union word computed on the fly: pf | padding_even (with virtual fix bit)
__device__ __forceinline__ unsigned union_word(int j, int fixw){
    int t = j >> 2;
    int y = t & (DD-1);
    int z = (t >> 7) & (DD-1);
    unsigned pe = 0;
    if (!(y & 1) && !(z & 1)){
        auto L = [&](int k) -> unsigned {
            unsigned v = g_pa[k];
            if (k == fixw) v |= 0x80000000u;
            return v;
        };
        unsigned q = L(j) | L(j+NW) | L(j+ROWW) | L(j+ROWW+NW);
        pe = (q | (q >> 1)) & 0x55555555u;
    }
    return g_pf[j] | pe;
}

// mask = dil3d(union), union computed inline, unpacked to floats
__global__ void k_dmask(float* __restrict__ out){
    int i = blockIdx.x*256 + threadIdx.x;
    int b = i >> 16;
    int fixw = (g_bp[b] == 0) ? (b*WPB + 127*ROWW + 127*NW + 3) : -1;
    unsigned r = dil3d_f([&](int j){ return union_word(j, fixw); }, i);
    float4* o = (float4*)(out + MASK_OFF + (size_t)i*32);
    #pragma unroll
    for (int j = 0; j < 8; j++){
        __stcs(&o[j], make_float4((r>>(4*j))&1 ? 1.f:0.f, (r>>(4*j+1))&1 ? 1.f:0.f,
                                  (r>>(4*j+2))&1 ? 1.f:0.f, (r>>(4*j+3))&1 ? 1.f:0.f));
    }
}

// ---------------- launch ----------------
extern "C" void kernel_launch(void* const* d_in, const int* in_sizes, int n_in,
                              void* d_out, int out_size){
    const float* sem   = (const float*)d_in[0];
    const float* depth = (const float*)d_in[1];
    const float* occ   = (const float*)d_in[2];
    const unsigned int* kept = (const unsigned int*)d_in[3];
    const float4* mapping = (const float4*)d_in[4];
    float* out = (float*)d_out;

    cudaFuncSetAttribute(k_small, cudaFuncAttributeMaxDynamicSharedMemorySize, SM2_BYTES);

    const int T = 256;
    const int WG = NWORDS/256;  // 512
    k_pix   <<<(BN*HW + T-1)/T, T>>>(sem, depth);
    k_small <<<BN, 512, SM2_BYTES>>>();
    k_feat  <<<dim3(30, 5, 30 + VZ), dim3(160, 2)>>>(occ, mapping, kept, out);
    k_dpk   <<<WG, T>>>();
    k_dmask <<<WG, T>>>(out);
}